// round 3
// baseline (speedup 1.0000x reference)
#include <cuda_runtime.h>
#include <math.h>

#define N_NODES 50000
#define N_EDGES 400000

// ---------------- scratch (static device globals; no allocation) ----------------
__device__ float g_erA[(size_t)N_EDGES * 64];
__device__ float g_eaA[(size_t)N_EDGES * 64];
__device__ float g_msg[(size_t)N_NODES * 256];
__device__ float g_nodesA[(size_t)N_NODES * 128];
__device__ float g_nodesB[(size_t)N_NODES * 128];
__device__ float g_deg[N_NODES];
__device__ float g_inv[N_NODES];   // 1/sqrt(deg)
__device__ float g_rdeg[N_NODES];  // 1/deg
__device__ int   g_perm[2 * N_NODES];
__device__ int   g_cnt[2];

// ---------------- f32x2 helpers ----------------
__device__ __forceinline__ unsigned long long packdup(float x) {
    unsigned long long r; unsigned int u = __float_as_uint(x);
    asm("mov.b64 %0, {%1, %1};" : "=l"(r) : "r"(u));
    return r;
}
__device__ __forceinline__ void ffma2(unsigned long long& acc, unsigned long long a, unsigned long long w) {
    asm("fma.rn.f32x2 %0, %1, %2, %0;" : "+l"(acc) : "l"(a), "l"(w));
}
__device__ __forceinline__ void unpack2(unsigned long long v, float& lo, float& hi) {
    unsigned int a, b;
    asm("mov.b64 {%0, %1}, %2;" : "=r"(a), "=r"(b) : "l"(v));
    lo = __uint_as_float(a); hi = __uint_as_float(b);
}
__device__ __forceinline__ void lds_wpair(unsigned int addr, unsigned long long& w01, unsigned long long& w23) {
    asm volatile("ld.shared.v2.b64 {%0, %1}, [%2];" : "=l"(w01), "=l"(w23) : "r"(addr));
}

// ---------------- fused MLP stage v2: 64 rows, 256 threads ----------------
// tx = tid&7 (8 column lanes, each owns DOUT_PAD/32 float4-quads)
// ty = tid>>3 (32 row lanes, rows ty and ty+32)
// Weights staged through smem in WCH-row chunks; inner math is FFMA2 (f32x2).
// out_s written with stride DOUT (unpadded).
template <int DIN, int DOUT, int DOUT_PAD, int ACT>  // ACT: 0 none, 1 relu, 2 silu
__device__ __forceinline__ void mlp2(const float* __restrict__ W,
                                     const float* __restrict__ B,
                                     const float* in_s, float* out_s,
                                     float* wtile, int tid) {
    const int tx = tid & 7;
    const int ty = tid >> 3;
    constexpr int NJ = DOUT_PAD / 32;               // quads per thread
    constexpr int WCH = (DIN % 32 == 0) ? 32 : 16;  // k-chunk rows

    unsigned long long acc[2][NJ][2];
#pragma unroll
    for (int r = 0; r < 2; r++)
#pragma unroll
        for (int j = 0; j < NJ; j++) { acc[r][j][0] = 0ull; acc[r][j][1] = 0ull; }

    const unsigned int wbase = (unsigned int)__cvta_generic_to_shared(wtile) + tx * 16;

    for (int k0 = 0; k0 < DIN; k0 += WCH) {
        __syncthreads();
        for (int idx = tid; idx < WCH * DOUT_PAD; idx += 256) {
            int kk = idx / DOUT_PAD, o = idx % DOUT_PAD;
            wtile[idx] = (o < DOUT) ? W[(k0 + kk) * DOUT + o] : 0.f;
        }
        __syncthreads();
#pragma unroll
        for (int kb = 0; kb < WCH; kb += 4) {
            float4 a0v = *(const float4*)(in_s + ty * DIN + k0 + kb);
            float4 a1v = *(const float4*)(in_s + (ty + 32) * DIN + k0 + kb);
            const float* a0f = (const float*)&a0v;
            const float* a1f = (const float*)&a1v;
#pragma unroll
            for (int kk = 0; kk < 4; kk++) {
                unsigned long long pa0 = packdup(a0f[kk]);
                unsigned long long pa1 = packdup(a1f[kk]);
#pragma unroll
                for (int j = 0; j < NJ; j++) {
                    unsigned long long w01, w23;
                    lds_wpair(wbase + ((kb + kk) * DOUT_PAD + j * 32) * 4, w01, w23);
                    ffma2(acc[0][j][0], pa0, w01);
                    ffma2(acc[0][j][1], pa0, w23);
                    ffma2(acc[1][j][0], pa1, w01);
                    ffma2(acc[1][j][1], pa1, w23);
                }
            }
        }
    }
    // epilogue
#pragma unroll
    for (int j = 0; j < NJ; j++) {
#pragma unroll
        for (int h = 0; h < 2; h++) {
            int o = (j * 8 + tx) * 4 + h * 2;
            float b0 = (o < DOUT) ? B[o] : 0.f;
            float b1 = (o + 1 < DOUT) ? B[o + 1] : 0.f;
#pragma unroll
            for (int r = 0; r < 2; r++) {
                int row = ty + r * 32;
                float v0, v1;
                unpack2(acc[r][j][h], v0, v1);
                v0 += b0; v1 += b1;
                if (ACT == 1) { v0 = fmaxf(v0, 0.f); v1 = fmaxf(v1, 0.f); }
                if (ACT == 2) {
                    v0 = v0 / (1.f + expf(-v0));
                    v1 = v1 / (1.f + expf(-v1));
                }
                if (o < DOUT)     out_s[row * DOUT + o] = v0;
                if (o + 1 < DOUT) out_s[row * DOUT + o + 1] = v1;
            }
        }
    }
}

// ---------------- degree ----------------
__global__ void zero_deg_kernel() {
    int i = blockIdx.x * blockDim.x + threadIdx.x;
    if (i < N_NODES) g_deg[i] = 0.f;
}
__global__ void deg_kernel(const int* __restrict__ dst) {
    int e = blockIdx.x * blockDim.x + threadIdx.x;
    if (e < N_EDGES) atomicAdd(&g_deg[dst[e]], 1.0f);
}
__global__ void inv_kernel() {
    int i = blockIdx.x * blockDim.x + threadIdx.x;
    if (i < N_NODES) {
        float d = g_deg[i];
        g_inv[i] = 1.0f / sqrtf(d);
        g_rdeg[i] = 1.0f / d;
    }
}

// ---------------- fused edge MLP (layer 0 only; layer-1 output is dead) ----------------
// 384 -> 192 -> 96 -> 48 -> 32 -> 64 (relu each) -> 128 (linear); 64 edges/block
extern "C" __global__ void __launch_bounds__(256)
edge_mlp_kernel(const float* __restrict__ nodes, const float* __restrict__ er,
                const float* __restrict__ ea, const int* __restrict__ src,
                const int* __restrict__ dst,
                const float* W0, const float* B0, const float* W1, const float* B1,
                const float* W2, const float* B2, const float* W3, const float* B3,
                const float* W4, const float* B4, const float* W5, const float* B5,
                float* __restrict__ er_out, float* __restrict__ ea_out) {
    extern __shared__ float smem[];
    float* buf0 = smem;                 // 64*384
    float* buf1 = buf0 + 64 * 384;      // 64*192
    float* wtile = buf1 + 64 * 192;     // 32*192
    __shared__ int sidx[64], didx[64];

    int tid = threadIdx.x;
    int e0 = blockIdx.x * 64;
    if (tid < 64) {
        sidx[tid] = src[e0 + tid];
        didx[tid] = dst[e0 + tid];
    }
    __syncthreads();

    // gather input quads: [nodes[src] | nodes[dst] | er | ea]  (96 quads/row)
    for (int q = tid; q < 64 * 96; q += 256) {
        int e = q / 96, cq = q % 96;
        float4 v;
        if (cq < 32)       v = *(const float4*)(nodes + (size_t)sidx[e] * 128 + cq * 4);
        else if (cq < 64)  v = *(const float4*)(nodes + (size_t)didx[e] * 128 + (cq - 32) * 4);
        else if (cq < 80)  v = *(const float4*)(er + (size_t)(e0 + e) * 64 + (cq - 64) * 4);
        else               v = *(const float4*)(ea + (size_t)(e0 + e) * 64 + (cq - 80) * 4);
        *(float4*)(buf0 + (size_t)q * 4) = v;
    }

    mlp2<384, 192, 192, 1>(W0, B0, buf0, buf1, wtile, tid);
    mlp2<192,  96,  96, 1>(W1, B1, buf1, buf0, wtile, tid);
    mlp2< 96,  48,  64, 1>(W2, B2, buf0, buf1, wtile, tid);
    mlp2< 48,  32,  32, 1>(W3, B3, buf1, buf0, wtile, tid);
    mlp2< 32,  64,  64, 1>(W4, B4, buf0, buf1, wtile, tid);
    mlp2< 64, 128, 128, 0>(W5, B5, buf1, buf0, wtile, tid);
    __syncthreads();

    for (int q = tid; q < 64 * 32; q += 256) {
        int e = q / 32, cq = q % 32;
        float4 v = *(const float4*)(buf0 + (size_t)(e * 32 + cq) * 4);
        if (cq < 16) *(float4*)(er_out + (size_t)(e0 + e) * 64 + cq * 4) = v;
        else         *(float4*)(ea_out + (size_t)(e0 + e) * 64 + (cq - 16) * 4) = v;
    }
}

// ---------------- message accumulation ----------------
__global__ void zero_msg_kernel() {
    size_t q = (size_t)blockIdx.x * blockDim.x + threadIdx.x;
    if (q < (size_t)N_NODES * 64) *(float4*)(g_msg + q * 4) = make_float4(0.f, 0.f, 0.f, 0.f);
}
// sub[e] = concat(nodes[src[src[e]]], er[e], ea[e]) / deg[src[e]]; segsum over dst
extern "C" __global__ void __launch_bounds__(256)
msg_kernel(const float* __restrict__ nodes, const float* __restrict__ er,
           const float* __restrict__ ea, const int* __restrict__ src,
           const int* __restrict__ dst) {
    int e = blockIdx.x;
    int c = threadIdx.x;
    int s = src[e];
    int d = dst[e];
    float v;
    if (c < 128) {
        int j = src[s];            // double gather, matching reference
        v = nodes[(size_t)j * 128 + c];
    } else if (c < 192) {
        v = er[(size_t)e * 64 + (c - 128)];
    } else {
        v = ea[(size_t)e * 64 + (c - 192)];
    }
    v = v * g_rdeg[s];
    atomicAdd(&g_msg[(size_t)d * 256 + c], v);
}

// ---------------- node update: silu((msg(+self))*inv @ Wn + bn) ----------------
extern "C" __global__ void __launch_bounds__(256)
node_kernel(const float* __restrict__ nodes_in, const float* __restrict__ Wn,
            const float* __restrict__ bn, float* __restrict__ nodes_out) {
    extern __shared__ float smem[];
    float* buf0 = smem;               // 64*256
    float* buf1 = buf0 + 64 * 256;    // 64*128
    float* wtile = buf1 + 64 * 128;   // 32*128
    int tid = threadIdx.x;
    int n0 = blockIdx.x * 64;

    for (int q = tid; q < 64 * 64; q += 256) {
        int n = q / 64, kq = q % 64;
        int node = n0 + n;
        float4 v = make_float4(0.f, 0.f, 0.f, 0.f);
        if (node < N_NODES) {
            float inv = g_inv[node];
            float4 m = *(const float4*)(g_msg + (size_t)node * 256 + kq * 4);
            if (kq < 32) {
                float4 x = *(const float4*)(nodes_in + (size_t)node * 128 + kq * 4);
                m.x += x.x * inv; m.y += x.y * inv; m.z += x.z * inv; m.w += x.w * inv;
            }
            v = make_float4(m.x * inv, m.y * inv, m.z * inv, m.w * inv);
        }
        *(float4*)(buf0 + (size_t)q * 4) = v;
    }

    mlp2<256, 128, 128, 2>(Wn, bn, buf0, buf1, wtile, tid);
    __syncthreads();

    for (int q = tid; q < 64 * 32; q += 256) {
        int n = q / 32, cq = q % 32;
        int node = n0 + n;
        if (node < N_NODES)
            *(float4*)(nodes_out + (size_t)node * 128 + cq * 4) =
                *(const float4*)(buf1 + (size_t)q * 4);
    }
}

// ---------------- type compaction + heads ----------------
__global__ void zero_cnt_kernel() {
    if (threadIdx.x < 2 && blockIdx.x == 0) g_cnt[threadIdx.x] = 0;
}
__global__ void compact_kernel(const int* __restrict__ atom_type) {
    int i = blockIdx.x * blockDim.x + threadIdx.x;
    if (i < N_NODES) {
        int t = atom_type[i];
        int p = atomicAdd(&g_cnt[t], 1);
        g_perm[t * N_NODES + p] = i;
    }
}

// head: 128 ->(relu) 128 x4 -> 169 (linear); weights already offset per type
extern "C" __global__ void __launch_bounds__(256)
head_kernel(int t, const float* __restrict__ nodes,
            const float* W0, const float* B0, const float* W1, const float* B1,
            const float* W2, const float* B2, const float* W3, const float* B3,
            const float* W4, const float* B4, float* __restrict__ out) {
    extern __shared__ float smem[];
    float* buf0 = smem;               // 64*128
    float* buf1 = buf0 + 64 * 128;    // 64*192
    float* wtile = buf1 + 64 * 192;   // 32*192
    __shared__ int nid[64];

    int tid = threadIdx.x;
    int cnt = g_cnt[t];
    int i0 = blockIdx.x * 64;
    if (i0 >= cnt) return;
    if (tid < 64) nid[tid] = (i0 + tid < cnt) ? g_perm[t * N_NODES + i0 + tid] : -1;
    __syncthreads();

    for (int q = tid; q < 64 * 32; q += 256) {
        int n = q / 32, cq = q % 32;
        float4 v = make_float4(0.f, 0.f, 0.f, 0.f);
        if (nid[n] >= 0)
            v = *(const float4*)(nodes + (size_t)nid[n] * 128 + cq * 4);
        *(float4*)(buf0 + (size_t)q * 4) = v;
    }

    mlp2<128, 128, 128, 1>(W0, B0, buf0, buf1, wtile, tid);
    mlp2<128, 128, 128, 1>(W1, B1, buf1, buf0, wtile, tid);
    mlp2<128, 128, 128, 1>(W2, B2, buf0, buf1, wtile, tid);
    mlp2<128, 128, 128, 1>(W3, B3, buf1, buf0, wtile, tid);
    mlp2<128, 169, 192, 0>(W4, B4, buf0, buf1, wtile, tid);
    __syncthreads();

    for (int idx = tid; idx < 64 * 169; idx += 256) {
        int n = idx / 169, c = idx % 169;
        if (nid[n] >= 0) out[(size_t)nid[n] * 169 + c] = buf1[idx];
    }
}

// ---------------- launch ----------------
extern "C" void kernel_launch(void* const* d_in, const int* in_sizes, int n_in,
                              void* d_out, int out_size) {
    const float* node_features = (const float*)d_in[0];
    const float* edge_radial   = (const float*)d_in[1];
    const float* edge_angular  = (const float*)d_in[2];
    const int*   edge_index    = (const int*)d_in[3];
    const int*   atom_type     = (const int*)d_in[4];
    const float* We[6]; const float* be[6];
    for (int i = 0; i < 6; i++) { We[i] = (const float*)d_in[5 + 2 * i]; be[i] = (const float*)d_in[6 + 2 * i]; }
    const float* Wn = (const float*)d_in[17];
    const float* bn = (const float*)d_in[18];
    const float* Wh[5]; const float* bh[5];
    for (int i = 0; i < 5; i++) { Wh[i] = (const float*)d_in[19 + 2 * i]; bh[i] = (const float*)d_in[20 + 2 * i]; }
    const int* src = edge_index;
    const int* dst = edge_index + N_EDGES;
    float* out = (float*)d_out;

    const int SM_EDGE = (64 * 384 + 64 * 192 + 32 * 192) * 4;   // 172032 B
    const int SM_NODE = (64 * 256 + 64 * 128 + 32 * 128) * 4;   // 114688 B
    const int SM_HEAD = (64 * 128 + 64 * 192 + 32 * 192) * 4;   // 106496 B
    cudaFuncSetAttribute(edge_mlp_kernel, cudaFuncAttributeMaxDynamicSharedMemorySize, SM_EDGE);
    cudaFuncSetAttribute(node_kernel,     cudaFuncAttributeMaxDynamicSharedMemorySize, SM_NODE);
    cudaFuncSetAttribute(head_kernel,     cudaFuncAttributeMaxDynamicSharedMemorySize, SM_HEAD);

    // degree (static over layers)
    zero_deg_kernel<<<(N_NODES + 255) / 256, 256>>>();
    deg_kernel<<<(N_EDGES + 255) / 256, 256>>>(dst);
    inv_kernel<<<(N_NODES + 255) / 256, 256>>>();

    float* erA = nullptr; float* eaA = nullptr;
    float* nodesA = nullptr; float* nodesB = nullptr;
    cudaGetSymbolAddress((void**)&erA, g_erA);
    cudaGetSymbolAddress((void**)&eaA, g_eaA);
    cudaGetSymbolAddress((void**)&nodesA, g_nodesA);
    cudaGetSymbolAddress((void**)&nodesB, g_nodesB);

    // ---- layer 0 ----
    edge_mlp_kernel<<<N_EDGES / 64, 256, SM_EDGE>>>(
        node_features, edge_radial, edge_angular, src, dst,
        We[0], be[0], We[1], be[1], We[2], be[2],
        We[3], be[3], We[4], be[4], We[5], be[5],
        erA, eaA);
    zero_msg_kernel<<<(int)(((size_t)N_NODES * 64 + 255) / 256), 256>>>();
    msg_kernel<<<N_EDGES, 256>>>(node_features, edge_radial, edge_angular, src, dst);
    node_kernel<<<(N_NODES + 63) / 64, 256, SM_NODE>>>(node_features, Wn, bn, nodesA);

    // ---- layer 1 (edge MLP output is unused -> skipped) ----
    zero_msg_kernel<<<(int)(((size_t)N_NODES * 64 + 255) / 256), 256>>>();
    msg_kernel<<<N_EDGES, 256>>>(nodesA, erA, eaA, src, dst);
    node_kernel<<<(N_NODES + 63) / 64, 256, SM_NODE>>>(nodesA, Wn + 256 * 128, bn + 128, nodesB);

    // ---- heads (per-type compaction, compute only the selected head) ----
    zero_cnt_kernel<<<1, 32>>>();
    compact_kernel<<<(N_NODES + 255) / 256, 256>>>(atom_type);
    int hblocks = (N_NODES + 63) / 64;
    for (int t = 0; t < 2; t++) {
        head_kernel<<<hblocks, 256, SM_HEAD>>>(
            t, nodesB,
            Wh[0] + (size_t)t * 128 * 128, bh[0] + (size_t)t * 128,
            Wh[1] + (size_t)t * 128 * 128, bh[1] + (size_t)t * 128,
            Wh[2] + (size_t)t * 128 * 128, bh[2] + (size_t)t * 128,
            Wh[3] + (size_t)t * 128 * 128, bh[3] + (size_t)t * 128,
            Wh[4] + (size_t)t * 128 * 169, bh[4] + (size_t)t * 169,
            out);
    }
}

// round 4
// speedup vs baseline: 1.6683x; 1.6683x over previous
#include <cuda_runtime.h>
#include <math.h>

#define N_NODES 50000
#define N_EDGES 400000

// ---------------- scratch (static device globals; no allocation) ----------------
__device__ float g_erA[(size_t)N_EDGES * 64];
__device__ float g_eaA[(size_t)N_EDGES * 64];
__device__ float g_msg[(size_t)N_NODES * 256];
__device__ float g_nodesA[(size_t)N_NODES * 128];
__device__ float g_nodesB[(size_t)N_NODES * 128];
__device__ float g_deg[N_NODES];
__device__ float g_inv[N_NODES];   // 1/sqrt(deg)
__device__ float g_rdeg[N_NODES];  // 1/deg
__device__ int   g_perm[2 * N_NODES];
__device__ int   g_cnt[2];

// ---------------- f32x2 helpers ----------------
__device__ __forceinline__ unsigned long long packdup(float x) {
    unsigned long long r; unsigned int u = __float_as_uint(x);
    asm("mov.b64 %0, {%1, %1};" : "=l"(r) : "r"(u));
    return r;
}
__device__ __forceinline__ void ffma2(unsigned long long& acc, unsigned long long a, unsigned long long w) {
    asm("fma.rn.f32x2 %0, %1, %2, %0;" : "+l"(acc) : "l"(a), "l"(w));
}
__device__ __forceinline__ void unpack2(unsigned long long v, float& lo, float& hi) {
    unsigned int a, b;
    asm("mov.b64 {%0, %1}, %2;" : "=r"(a), "=r"(b) : "l"(v));
    lo = __uint_as_float(a); hi = __uint_as_float(b);
}
__device__ __forceinline__ void lds_wpair(unsigned int addr, unsigned long long& w01, unsigned long long& w23) {
    asm volatile("ld.shared.v2.b64 {%0, %1}, [%2];" : "=l"(w01), "=l"(w23) : "r"(addr));
}

// ================= fused MLP stage v3 =================
// 256 threads = 16 col-lanes (tx) x 16 row-lanes (ty); 64 rows, 4 rows/thread.
// Each thread owns DOUT_PAD/16 output columns as NJ=DOUT_PAD/64 float-quads.
// Weights staged through smem in 16-row k-chunks; math in FFMA2 (f32x2).
// in_s stride DIN, out_s stride DOUT (unpadded).
template <int DIN, int DOUT, int DOUT_PAD, int ACT>  // ACT: 0 none, 1 relu, 2 silu
__device__ __forceinline__ void mlp3(const float* __restrict__ W,
                                     const float* __restrict__ B,
                                     const float* in_s, float* out_s,
                                     float* wtile, int tid) {
    const int tx = tid & 15;
    const int ty = tid >> 4;
    constexpr int NJ = DOUT_PAD / 64;

    unsigned long long acc[4][NJ][2];
#pragma unroll
    for (int r = 0; r < 4; r++)
#pragma unroll
        for (int j = 0; j < NJ; j++) { acc[r][j][0] = 0ull; acc[r][j][1] = 0ull; }

    const unsigned int wbase = (unsigned int)__cvta_generic_to_shared(wtile) + tx * 16;

    for (int k0 = 0; k0 < DIN; k0 += 16) {
        __syncthreads();
        if constexpr (DOUT % 2 == 0) {
            for (int idx = tid; idx < 16 * (DOUT_PAD / 2); idx += 256) {
                int kk = idx / (DOUT_PAD / 2), oc = idx % (DOUT_PAD / 2);
                float2 v = make_float2(0.f, 0.f);
                if (2 * oc < DOUT) v = *(const float2*)(W + (size_t)(k0 + kk) * DOUT + 2 * oc);
                *(float2*)(wtile + kk * DOUT_PAD + 2 * oc) = v;
            }
        } else {
            for (int idx = tid; idx < 16 * DOUT_PAD; idx += 256) {
                int kk = idx / DOUT_PAD, o = idx % DOUT_PAD;
                wtile[idx] = (o < DOUT) ? W[(size_t)(k0 + kk) * DOUT + o] : 0.f;
            }
        }
        __syncthreads();
#pragma unroll
        for (int kb = 0; kb < 16; kb += 4) {
            float4 av[4];
#pragma unroll
            for (int r = 0; r < 4; r++)
                av[r] = *(const float4*)(in_s + (size_t)(ty + r * 16) * DIN + k0 + kb);
#pragma unroll
            for (int kk = 0; kk < 4; kk++) {
                unsigned long long pa[4];
#pragma unroll
                for (int r = 0; r < 4; r++) pa[r] = packdup(((const float*)&av[r])[kk]);
#pragma unroll
                for (int j = 0; j < NJ; j++) {
                    unsigned long long w01, w23;
                    lds_wpair(wbase + (unsigned)((kb + kk) * DOUT_PAD + j * 64) * 4, w01, w23);
#pragma unroll
                    for (int r = 0; r < 4; r++) {
                        ffma2(acc[r][j][0], pa[r], w01);
                        ffma2(acc[r][j][1], pa[r], w23);
                    }
                }
            }
        }
    }
    // epilogue
#pragma unroll
    for (int j = 0; j < NJ; j++) {
#pragma unroll
        for (int h = 0; h < 2; h++) {
            int o = j * 64 + tx * 4 + h * 2;
            float b0 = (o < DOUT) ? B[o] : 0.f;
            float b1 = (o + 1 < DOUT) ? B[o + 1] : 0.f;
#pragma unroll
            for (int r = 0; r < 4; r++) {
                int row = ty + r * 16;
                float v0, v1;
                unpack2(acc[r][j][h], v0, v1);
                v0 += b0; v1 += b1;
                if (ACT == 1) { v0 = fmaxf(v0, 0.f); v1 = fmaxf(v1, 0.f); }
                if (ACT == 2) {
                    v0 = v0 / (1.f + expf(-v0));
                    v1 = v1 / (1.f + expf(-v1));
                }
                if (o < DOUT)     out_s[(size_t)row * DOUT + o] = v0;
                if (o + 1 < DOUT) out_s[(size_t)row * DOUT + o + 1] = v1;
            }
        }
    }
}

// ---------------- degree ----------------
__global__ void zero_deg_kernel() {
    int i = blockIdx.x * blockDim.x + threadIdx.x;
    if (i < N_NODES) g_deg[i] = 0.f;
}
__global__ void deg_kernel(const int* __restrict__ dst) {
    int e = blockIdx.x * blockDim.x + threadIdx.x;
    if (e < N_EDGES) atomicAdd(&g_deg[dst[e]], 1.0f);
}
__global__ void inv_kernel() {
    int i = blockIdx.x * blockDim.x + threadIdx.x;
    if (i < N_NODES) {
        float d = g_deg[i];
        g_inv[i] = 1.0f / sqrtf(d);
        g_rdeg[i] = 1.0f / d;
    }
}

// ---------------- edge stage 0: gather-streamed 384 -> 192 (relu) ----------------
__device__ __forceinline__ float4 es0_gather(const float* __restrict__ nodes,
                                             const float* __restrict__ er,
                                             const float* __restrict__ ea,
                                             const int* sidx, const int* didx,
                                             int e0, int grow, int cb) {
    if (cb < 128)      return *(const float4*)(nodes + (size_t)sidx[grow] * 128 + cb);
    else if (cb < 256) return *(const float4*)(nodes + (size_t)didx[grow] * 128 + (cb - 128));
    else if (cb < 320) return *(const float4*)(er + (size_t)(e0 + grow) * 64 + (cb - 256));
    else               return *(const float4*)(ea + (size_t)(e0 + grow) * 64 + (cb - 320));
}

__device__ __forceinline__ void edge_stage0(const float* __restrict__ nodes,
                                            const float* __restrict__ er,
                                            const float* __restrict__ ea,
                                            const int* sidx, const int* didx, int e0,
                                            const float* __restrict__ W,
                                            const float* __restrict__ B,
                                            float* intile, float* wtile,
                                            float* out_s, int tid) {
    const int tx = tid & 15;
    const int ty = tid >> 4;
    constexpr int NJ = 3;  // 192/64
    unsigned long long acc[4][NJ][2];
#pragma unroll
    for (int r = 0; r < 4; r++)
#pragma unroll
        for (int j = 0; j < NJ; j++) { acc[r][j][0] = 0ull; acc[r][j][1] = 0ull; }

    const unsigned int wbase = (unsigned int)__cvta_generic_to_shared(wtile) + tx * 16;
    const int grow = tid >> 2;          // 0..63
    const int gq = (tid & 3) * 4;       // 0,4,8,12

    float4 pre = es0_gather(nodes, er, ea, sidx, didx, e0, grow, gq);

    for (int k0 = 0; k0 < 384; k0 += 16) {
        __syncthreads();
        *(float4*)(intile + grow * 16 + gq) = pre;
        for (int idx = tid; idx < 16 * 96; idx += 256) {
            int kk = idx / 96, oc = idx % 96;
            *(float2*)(wtile + kk * 192 + 2 * oc) = *(const float2*)(W + (size_t)(k0 + kk) * 192 + 2 * oc);
        }
        __syncthreads();
        if (k0 + 16 < 384)
            pre = es0_gather(nodes, er, ea, sidx, didx, e0, grow, k0 + 16 + gq);
#pragma unroll
        for (int kb = 0; kb < 16; kb += 4) {
            float4 av[4];
#pragma unroll
            for (int r = 0; r < 4; r++)
                av[r] = *(const float4*)(intile + (ty + r * 16) * 16 + kb);
#pragma unroll
            for (int kk = 0; kk < 4; kk++) {
                unsigned long long pa[4];
#pragma unroll
                for (int r = 0; r < 4; r++) pa[r] = packdup(((const float*)&av[r])[kk]);
#pragma unroll
                for (int j = 0; j < NJ; j++) {
                    unsigned long long w01, w23;
                    lds_wpair(wbase + (unsigned)((kb + kk) * 192 + j * 64) * 4, w01, w23);
#pragma unroll
                    for (int r = 0; r < 4; r++) {
                        ffma2(acc[r][j][0], pa[r], w01);
                        ffma2(acc[r][j][1], pa[r], w23);
                    }
                }
            }
        }
    }
#pragma unroll
    for (int j = 0; j < NJ; j++) {
#pragma unroll
        for (int h = 0; h < 2; h++) {
            int o = j * 64 + tx * 4 + h * 2;
            float b0 = B[o], b1 = B[o + 1];
#pragma unroll
            for (int r = 0; r < 4; r++) {
                int row = ty + r * 16;
                float v0, v1;
                unpack2(acc[r][j][h], v0, v1);
                v0 = fmaxf(v0 + b0, 0.f); v1 = fmaxf(v1 + b1, 0.f);
                out_s[(size_t)row * 192 + o] = v0;
                out_s[(size_t)row * 192 + o + 1] = v1;
            }
        }
    }
}

// ---------------- fused edge MLP (layer 0 only; layer-1 output is dead) ----------------
// 384 -> 192 -> 96 -> 48 -> 32 -> 64 (relu each) -> 128 (linear); 64 edges/block
extern "C" __global__ void __launch_bounds__(256, 2)
edge_mlp_kernel(const float* __restrict__ nodes, const float* __restrict__ er,
                const float* __restrict__ ea, const int* __restrict__ src,
                const int* __restrict__ dst,
                const float* W0, const float* B0, const float* W1, const float* B1,
                const float* W2, const float* B2, const float* W3, const float* B3,
                const float* W4, const float* B4, const float* W5, const float* B5,
                float* __restrict__ er_out, float* __restrict__ ea_out) {
    extern __shared__ float smem[];
    float* intile = smem;                  // 64*16     = 4KB
    float* bufA = intile + 64 * 16;        // 64*192    = 48KB
    float* bufB = bufA + 64 * 192;         // 64*128    = 32KB
    float* wtile = bufB + 64 * 128;        // 16*192    = 12KB
    __shared__ int sidx[64], didx[64];

    int tid = threadIdx.x;
    int e0 = blockIdx.x * 64;
    if (tid < 64) {
        sidx[tid] = src[e0 + tid];
        didx[tid] = dst[e0 + tid];
    }
    __syncthreads();

    edge_stage0(nodes, er, ea, sidx, didx, e0, W0, B0, intile, wtile, bufA, tid);
    mlp3<192,  96, 128, 1>(W1, B1, bufA, bufB, wtile, tid);
    mlp3< 96,  48,  64, 1>(W2, B2, bufB, bufA, wtile, tid);
    mlp3< 48,  32,  64, 1>(W3, B3, bufA, bufB, wtile, tid);
    mlp3< 32,  64,  64, 1>(W4, B4, bufB, bufA, wtile, tid);
    mlp3< 64, 128, 128, 0>(W5, B5, bufA, bufB, wtile, tid);
    __syncthreads();

    for (int q = tid; q < 64 * 32; q += 256) {
        int e = q / 32, cq = q % 32;
        float4 v = *(const float4*)(bufB + (size_t)(e * 32 + cq) * 4);
        if (cq < 16) *(float4*)(er_out + (size_t)(e0 + e) * 64 + cq * 4) = v;
        else         *(float4*)(ea_out + (size_t)(e0 + e) * 64 + (cq - 16) * 4) = v;
    }
}

// ---------------- message accumulation ----------------
// sub[e] = concat(nodes[src[src[e]]], er[e], ea[e]) / deg[src[e]]; segsum over dst
// 4 edges per block; vector reductions (red.global.add.v4.f32)
extern "C" __global__ void __launch_bounds__(256)
msg_kernel(const float* __restrict__ nodes, const float* __restrict__ er,
           const float* __restrict__ ea, const int* __restrict__ src,
           const int* __restrict__ dst) {
    int t = threadIdx.x;
    int e = blockIdx.x * 4 + (t >> 6);
    int c4 = (t & 63) * 4;
    int s = src[e];
    int d = dst[e];
    float4 v;
    if (c4 < 128) {
        int j = src[s];            // double gather, matching reference
        v = *(const float4*)(nodes + (size_t)j * 128 + c4);
    } else if (c4 < 192) {
        v = *(const float4*)(er + (size_t)e * 64 + (c4 - 128));
    } else {
        v = *(const float4*)(ea + (size_t)e * 64 + (c4 - 192));
    }
    float r = g_rdeg[s];
    v.x *= r; v.y *= r; v.z *= r; v.w *= r;
    float* p = &g_msg[(size_t)d * 256 + c4];
    asm volatile("red.global.add.v4.f32 [%0], {%1,%2,%3,%4};"
                 :: "l"(p), "f"(v.x), "f"(v.y), "f"(v.z), "f"(v.w) : "memory");
}

// ---------------- node update: silu((msg(+self))*inv @ Wn + bn) ----------------
extern "C" __global__ void __launch_bounds__(256, 2)
node_kernel(const float* __restrict__ nodes_in, const float* __restrict__ Wn,
            const float* __restrict__ bn, float* __restrict__ nodes_out) {
    extern __shared__ float smem[];
    float* buf0 = smem;               // 64*256 = 64KB
    float* buf1 = buf0 + 64 * 256;    // 64*128 = 32KB
    float* wtile = buf1 + 64 * 128;   // 16*128 = 8KB
    int tid = threadIdx.x;
    int n0 = blockIdx.x * 64;

    for (int q = tid; q < 64 * 64; q += 256) {
        int n = q / 64, kq = q % 64;
        int node = n0 + n;
        float4 v = make_float4(0.f, 0.f, 0.f, 0.f);
        if (node < N_NODES) {
            float inv = g_inv[node];
            float4 m = *(const float4*)(g_msg + (size_t)node * 256 + kq * 4);
            if (kq < 32) {
                float4 x = *(const float4*)(nodes_in + (size_t)node * 128 + kq * 4);
                m.x += x.x * inv; m.y += x.y * inv; m.z += x.z * inv; m.w += x.w * inv;
            }
            v = make_float4(m.x * inv, m.y * inv, m.z * inv, m.w * inv);
        }
        *(float4*)(buf0 + (size_t)q * 4) = v;
    }

    mlp3<256, 128, 128, 2>(Wn, bn, buf0, buf1, wtile, tid);
    __syncthreads();

    for (int q = tid; q < 64 * 32; q += 256) {
        int n = q / 32, cq = q % 32;
        int node = n0 + n;
        if (node < N_NODES)
            *(float4*)(nodes_out + (size_t)node * 128 + cq * 4) =
                *(const float4*)(buf1 + (size_t)q * 4);
    }
}

// ---------------- type compaction + heads ----------------
__global__ void zero_cnt_kernel() {
    if (threadIdx.x < 2 && blockIdx.x == 0) g_cnt[threadIdx.x] = 0;
}
__global__ void compact_kernel(const int* __restrict__ atom_type) {
    int i = blockIdx.x * blockDim.x + threadIdx.x;
    if (i < N_NODES) {
        int t = atom_type[i];
        int p = atomicAdd(&g_cnt[t], 1);
        g_perm[t * N_NODES + p] = i;
    }
}

// head: 128 ->(relu) 128 x4 -> 169 (linear); weights already offset per type
extern "C" __global__ void __launch_bounds__(256, 2)
head_kernel(int t, const float* __restrict__ nodes,
            const float* W0, const float* B0, const float* W1, const float* B1,
            const float* W2, const float* B2, const float* W3, const float* B3,
            const float* W4, const float* B4, float* __restrict__ out) {
    extern __shared__ float smem[];
    float* buf0 = smem;               // 64*128 = 32KB
    float* buf1 = buf0 + 64 * 128;    // 64*192 = 48KB
    float* wtile = buf1 + 64 * 192;   // 16*192 = 12KB
    __shared__ int nid[64];

    int tid = threadIdx.x;
    int cnt = g_cnt[t];
    int i0 = blockIdx.x * 64;
    if (i0 >= cnt) return;
    if (tid < 64) nid[tid] = (i0 + tid < cnt) ? g_perm[t * N_NODES + i0 + tid] : -1;
    __syncthreads();

    for (int q = tid; q < 64 * 32; q += 256) {
        int n = q / 32, cq = q % 32;
        float4 v = make_float4(0.f, 0.f, 0.f, 0.f);
        if (nid[n] >= 0)
            v = *(const float4*)(nodes + (size_t)nid[n] * 128 + cq * 4);
        *(float4*)(buf0 + (size_t)q * 4) = v;
    }

    mlp3<128, 128, 128, 1>(W0, B0, buf0, buf1, wtile, tid);
    mlp3<128, 128, 128, 1>(W1, B1, buf1, buf0, wtile, tid);
    mlp3<128, 128, 128, 1>(W2, B2, buf0, buf1, wtile, tid);
    mlp3<128, 128, 128, 1>(W3, B3, buf1, buf0, wtile, tid);
    mlp3<128, 169, 192, 0>(W4, B4, buf0, buf1, wtile, tid);
    __syncthreads();

    for (int idx = tid; idx < 64 * 169; idx += 256) {
        int n = idx / 169, c = idx % 169;
        if (nid[n] >= 0) out[(size_t)nid[n] * 169 + c] = buf1[idx];
    }
}

// ---------------- launch ----------------
extern "C" void kernel_launch(void* const* d_in, const int* in_sizes, int n_in,
                              void* d_out, int out_size) {
    const float* node_features = (const float*)d_in[0];
    const float* edge_radial   = (const float*)d_in[1];
    const float* edge_angular  = (const float*)d_in[2];
    const int*   edge_index    = (const int*)d_in[3];
    const int*   atom_type     = (const int*)d_in[4];
    const float* We[6]; const float* be[6];
    for (int i = 0; i < 6; i++) { We[i] = (const float*)d_in[5 + 2 * i]; be[i] = (const float*)d_in[6 + 2 * i]; }
    const float* Wn = (const float*)d_in[17];
    const float* bn = (const float*)d_in[18];
    const float* Wh[5]; const float* bh[5];
    for (int i = 0; i < 5; i++) { Wh[i] = (const float*)d_in[19 + 2 * i]; bh[i] = (const float*)d_in[20 + 2 * i]; }
    const int* src = edge_index;
    const int* dst = edge_index + N_EDGES;
    float* out = (float*)d_out;

    const int SM_EDGE = (64 * 16 + 64 * 192 + 64 * 128 + 16 * 192) * 4;  // 98304 B
    const int SM_NODE = (64 * 256 + 64 * 128 + 16 * 128) * 4;            // 106496 B
    const int SM_HEAD = (64 * 128 + 64 * 192 + 16 * 192) * 4;            // 94208 B
    cudaFuncSetAttribute(edge_mlp_kernel, cudaFuncAttributeMaxDynamicSharedMemorySize, SM_EDGE);
    cudaFuncSetAttribute(node_kernel,     cudaFuncAttributeMaxDynamicSharedMemorySize, SM_NODE);
    cudaFuncSetAttribute(head_kernel,     cudaFuncAttributeMaxDynamicSharedMemorySize, SM_HEAD);

    // degree (static over layers)
    zero_deg_kernel<<<(N_NODES + 255) / 256, 256>>>();
    deg_kernel<<<(N_EDGES + 255) / 256, 256>>>(dst);
    inv_kernel<<<(N_NODES + 255) / 256, 256>>>();

    float* erA = nullptr; float* eaA = nullptr;
    float* nodesA = nullptr; float* nodesB = nullptr;
    float* msgp = nullptr;
    cudaGetSymbolAddress((void**)&erA, g_erA);
    cudaGetSymbolAddress((void**)&eaA, g_eaA);
    cudaGetSymbolAddress((void**)&nodesA, g_nodesA);
    cudaGetSymbolAddress((void**)&nodesB, g_nodesB);
    cudaGetSymbolAddress((void**)&msgp, g_msg);

    // ---- layer 0 ----
    edge_mlp_kernel<<<N_EDGES / 64, 256, SM_EDGE>>>(
        node_features, edge_radial, edge_angular, src, dst,
        We[0], be[0], We[1], be[1], We[2], be[2],
        We[3], be[3], We[4], be[4], We[5], be[5],
        erA, eaA);
    cudaMemsetAsync(msgp, 0, (size_t)N_NODES * 256 * sizeof(float));
    msg_kernel<<<N_EDGES / 4, 256>>>(node_features, edge_radial, edge_angular, src, dst);
    node_kernel<<<(N_NODES + 63) / 64, 256, SM_NODE>>>(node_features, Wn, bn, nodesA);

    // ---- layer 1 (edge MLP output is unused -> skipped) ----
    cudaMemsetAsync(msgp, 0, (size_t)N_NODES * 256 * sizeof(float));
    msg_kernel<<<N_EDGES / 4, 256>>>(nodesA, erA, eaA, src, dst);
    node_kernel<<<(N_NODES + 63) / 64, 256, SM_NODE>>>(nodesA, Wn + 256 * 128, bn + 128, nodesB);

    // ---- heads (per-type compaction, compute only the selected head) ----
    zero_cnt_kernel<<<1, 32>>>();
    compact_kernel<<<(N_NODES + 255) / 256, 256>>>(atom_type);
    int hblocks = (N_NODES + 63) / 64;
    for (int t = 0; t < 2; t++) {
        head_kernel<<<hblocks, 256, SM_HEAD>>>(
            t, nodesB,
            Wh[0] + (size_t)t * 128 * 128, bh[0] + (size_t)t * 128,
            Wh[1] + (size_t)t * 128 * 128, bh[1] + (size_t)t * 128,
            Wh[2] + (size_t)t * 128 * 128, bh[2] + (size_t)t * 128,
            Wh[3] + (size_t)t * 128 * 128, bh[3] + (size_t)t * 128,
            Wh[4] + (size_t)t * 128 * 169, bh[4] + (size_t)t * 169,
            out);
    }
}